// round 8
// baseline (speedup 1.0000x reference)
#include <cuda_runtime.h>
#include <math.h>

// FFF: fast-feedforward conditional tree MLP.
// B=8192, D_in=D_out=2048, depth 11 -> 12 routing steps, 4095 nodes.
//
// k1 transpose_wout: W_out (2048 x 4095) -> g_WoutT (4095 x 2048).
// k2 route_kernel:   WARP-per-sample tree walk. x cached as 16 float4/lane.
//                    Per step: 16 coalesced LDG.128 + 64 FMA + 5 shfl.
//                    No smem, no __syncthreads -> short chain, many chains/SM,
//                    L1-bandwidth bound instead of latency bound.
// k3 out_kernel:     out[b] = sum_d g_d * W_outT[node_d]; 12 independent
//                    row gathers, fully unrolled, latency-immune.

#define DEPTH    11
#define NSTEPS   (DEPTH + 1)
#define N_NODES  4095
#define DDIM     2048
#define D4       (DDIM / 4)       // 512 float4 per row
#define BATCH    8192
#define RWARPS   8                // samples per route block
#define RTHREADS (RWARPS * 32)

__device__ float g_WoutT[(size_t)N_NODES * DDIM];
__device__ int   g_nodes[(size_t)BATCH * NSTEPS];
__device__ float g_gval [(size_t)BATCH * NSTEPS];

// 64x64 tile transpose, 256 threads, coalesced both sides.
__global__ __launch_bounds__(256) void transpose_wout(const float* __restrict__ Wout) {
    __shared__ float tile[64][65];
    const int n0 = blockIdx.x * 64;   // node dim (4095)
    const int o0 = blockIdx.y * 64;   // output dim (2048)
    const int tid = threadIdx.x;

    #pragma unroll
    for (int k = 0; k < 16; ++k) {
        int e = k * 256 + tid;
        int ol = e >> 6;
        int nl = e & 63;
        int n = n0 + nl;
        float v = 0.f;
        if (n < N_NODES)
            v = Wout[(size_t)(o0 + ol) * N_NODES + n];
        tile[nl][ol] = v;
    }
    __syncthreads();

    #pragma unroll
    for (int k = 0; k < 16; ++k) {
        int e = k * 256 + tid;
        int nl = e >> 6;
        int ol = e & 63;
        int n = n0 + nl;
        if (n < N_NODES)
            g_WoutT[(size_t)n * DDIM + (o0 + ol)] = tile[nl][ol];
    }
}

__device__ __forceinline__ float dot4(float4 a, float4 b) {
    return fmaf(a.x, b.x, fmaf(a.y, b.y, fmaf(a.z, b.z, a.w * b.w)));
}

__device__ __forceinline__ void fma4(float4& a, float g, float4 v) {
    a.x = fmaf(g, v.x, a.x);
    a.y = fmaf(g, v.y, a.y);
    a.z = fmaf(g, v.z, a.z);
    a.w = fmaf(g, v.w, a.w);
}

// Warp-per-sample routing. 8 warps (samples) per block.
__global__ __launch_bounds__(RTHREADS, 2) void route_kernel(
    const float* __restrict__ x,
    const float* __restrict__ Win)
{
    const int warp = threadIdx.x >> 5;
    const int lane = threadIdx.x & 31;
    const int b    = blockIdx.x * RWARPS + warp;

    // x row: lane-strided float4 (lane + 32*i), fully coalesced.
    const float4* __restrict__ x4   = reinterpret_cast<const float4*>(x) + (size_t)b * D4 + lane;
    const float4* __restrict__ Win4 = reinterpret_cast<const float4*>(Win);

    float4 xr[16];
    #pragma unroll
    for (int i = 0; i < 16; ++i)
        xr[i] = x4[i * 32];

    int node = 0;
    #pragma unroll
    for (int d = 0; d < NSTEPS; ++d) {
        const float4* __restrict__ wr = Win4 + (size_t)node * D4 + lane;

        float p = 0.f;
        #pragma unroll
        for (int i = 0; i < 16; ++i)
            p += dot4(wr[i * 32], xr[i]);

        // Warp reduce (fixed order -> deterministic), then broadcast.
        #pragma unroll
        for (int off = 16; off > 0; off >>= 1)
            p += __shfl_down_sync(0xffffffffu, p, off);
        float score = __shfl_sync(0xffffffffu, p, 0);

        if (lane == 0) {
            // Exact GELU: 0.5*s*(1+erf(s/sqrt(2)))
            float g = 0.5f * score * (1.0f + erff(score * 0.70710678118654752f));
            g_nodes[(size_t)b * NSTEPS + d] = node;
            g_gval [(size_t)b * NSTEPS + d] = g;
        }

        node = node * 2 + 1 + (score >= 0.0f ? 1 : 0);
    }
}

// Output accumulation: fully parallel, 12 independent row gathers per sample.
__global__ __launch_bounds__(128, 8) void out_kernel(
    float* __restrict__ out)
{
    const int b   = blockIdx.x;
    const int tid = threadIdx.x;

    const float4* __restrict__ Wt4 = reinterpret_cast<const float4*>(g_WoutT);

    int   nd[NSTEPS];
    float gg[NSTEPS];
    #pragma unroll
    for (int d = 0; d < NSTEPS; ++d) {
        nd[d] = g_nodes[(size_t)b * NSTEPS + d];
        gg[d] = g_gval [(size_t)b * NSTEPS + d];
    }

    float4 a0 = make_float4(0.f, 0.f, 0.f, 0.f);
    float4 a1 = make_float4(0.f, 0.f, 0.f, 0.f);
    float4 a2 = make_float4(0.f, 0.f, 0.f, 0.f);
    float4 a3 = make_float4(0.f, 0.f, 0.f, 0.f);

    #pragma unroll
    for (int d = 0; d < NSTEPS; ++d) {
        const float4* __restrict__ vr = Wt4 + (size_t)nd[d] * D4;
        float g = gg[d];
        fma4(a0, g, vr[tid]);
        fma4(a1, g, vr[tid + 128]);
        fma4(a2, g, vr[tid + 256]);
        fma4(a3, g, vr[tid + 384]);
    }

    float4* __restrict__ o4 = reinterpret_cast<float4*>(out) + (size_t)b * D4;
    o4[tid]       = a0;
    o4[tid + 128] = a1;
    o4[tid + 256] = a2;
    o4[tid + 384] = a3;
}

extern "C" void kernel_launch(void* const* d_in, const int* in_sizes, int n_in,
                              void* d_out, int out_size)
{
    const float* x    = (const float*)d_in[0];   // (8192, 2048)
    const float* Win  = (const float*)d_in[1];   // (4095, 2048)
    const float* Wout = (const float*)d_in[2];   // (2048, 4095)
    float* out = (float*)d_out;                  // (8192, 2048)

    dim3 tg((N_NODES + 63) / 64, DDIM / 64);     // 64 x 32 tiles
    transpose_wout<<<tg, 256>>>(Wout);

    route_kernel<<<BATCH / RWARPS, RTHREADS>>>(x, Win);
    out_kernel<<<BATCH, 128>>>(out);
}

// round 9
// speedup vs baseline: 1.0359x; 1.0359x over previous
#include <cuda_runtime.h>
#include <math.h>

// FFF: fast-feedforward conditional tree MLP.
// B=8192, D_in=D_out=2048, depth 11 -> 12 routing steps, 4095 nodes.
//
// k1 transpose_wout: W_out -> g_WoutT, run on a forked stream concurrently
//                    with route (independent inputs), joined before out.
// k2 route_kernel:   128-thr block routes TWO samples, software-pipelined:
//                    B's load overlaps A's dot+reduce and vice versa, so L2
//                    latency is off the serial chain. Fixed-order reductions
//                    (deterministic fp32 signs).
// k3 out_kernel:     out[b] = sum_d g_d * W_outT[node_d]; 12 independent row
//                    gathers, latency-immune.

#define DEPTH    11
#define NSTEPS   (DEPTH + 1)
#define N_NODES  4095
#define DDIM     2048
#define D4       (DDIM / 4)     // 512 float4 per row
#define BATCH    8192

__device__ float g_WoutT[(size_t)N_NODES * DDIM];
__device__ int   g_nodes[(size_t)BATCH * NSTEPS];
__device__ float g_gval [(size_t)BATCH * NSTEPS];

// 64x64 tile transpose, 256 threads, coalesced both sides.
__global__ __launch_bounds__(256) void transpose_wout(const float* __restrict__ Wout) {
    __shared__ float tile[64][65];
    const int n0 = blockIdx.x * 64;
    const int o0 = blockIdx.y * 64;
    const int tid = threadIdx.x;

    #pragma unroll
    for (int k = 0; k < 16; ++k) {
        int e = k * 256 + tid;
        int ol = e >> 6;
        int nl = e & 63;
        int n = n0 + nl;
        float v = 0.f;
        if (n < N_NODES)
            v = Wout[(size_t)(o0 + ol) * N_NODES + n];
        tile[nl][ol] = v;
    }
    __syncthreads();

    #pragma unroll
    for (int k = 0; k < 16; ++k) {
        int e = k * 256 + tid;
        int nl = e >> 6;
        int ol = e & 63;
        int n = n0 + nl;
        if (n < N_NODES)
            g_WoutT[(size_t)n * DDIM + (o0 + ol)] = tile[nl][ol];
    }
}

__device__ __forceinline__ float dot4(float4 a, float4 b) {
    return fmaf(a.x, b.x, fmaf(a.y, b.y, fmaf(a.z, b.z, a.w * b.w)));
}

__device__ __forceinline__ void fma4(float4& a, float g, float4 v) {
    a.x = fmaf(g, v.x, a.x);
    a.y = fmaf(g, v.y, a.y);
    a.z = fmaf(g, v.z, a.z);
    a.w = fmaf(g, v.w, a.w);
}

__device__ __forceinline__ float gelu_exact(float s) {
    return 0.5f * s * (1.0f + erff(s * 0.70710678118654752f));
}

// Two samples per 128-thread block, software-pipelined.
__global__ __launch_bounds__(128, 6) void route_kernel(
    const float* __restrict__ x,
    const float* __restrict__ Win)
{
    const int tid  = threadIdx.x;
    const int lane = tid & 31;
    const int warp = tid >> 5;
    const int bA   = blockIdx.x * 2;
    const int bB   = bA + 1;

    const float4* __restrict__ Win4 = reinterpret_cast<const float4*>(Win);
    const float4* __restrict__ xa4  = reinterpret_cast<const float4*>(x) + (size_t)bA * D4;
    const float4* __restrict__ xb4  = reinterpret_cast<const float4*>(x) + (size_t)bB * D4;

    float4 xA0 = xa4[tid], xA1 = xa4[tid + 128], xA2 = xa4[tid + 256], xA3 = xa4[tid + 384];
    float4 xB0 = xb4[tid], xB1 = xb4[tid + 128], xB2 = xb4[tid + 256], xB3 = xb4[tid + 384];

    __shared__ float redA[4], redB[4];

    int nodeA = 0, nodeB = 0;

    // Preload A's root row.
    const float4* wr = Win4;  // node 0
    float4 wA0 = wr[tid], wA1 = wr[tid + 128], wA2 = wr[tid + 256], wA3 = wr[tid + 384];

    #pragma unroll
    for (int d = 0; d < NSTEPS; ++d) {
        // Issue B's row load for this step; it lands during A's phase.
        const float4* wrB = Win4 + (size_t)nodeB * D4;
        float4 wB0 = wrB[tid], wB1 = wrB[tid + 128], wB2 = wrB[tid + 256], wB3 = wrB[tid + 384];

        // ---- Phase A: dot + reduce + select ----
        {
            float p = dot4(wA0, xA0);
            p += dot4(wA1, xA1);
            p += dot4(wA2, xA2);
            p += dot4(wA3, xA3);
            #pragma unroll
            for (int off = 16; off > 0; off >>= 1)
                p += __shfl_down_sync(0xffffffffu, p, off);
            if (lane == 0) redA[warp] = p;
            __syncthreads();
            float sA = (redA[0] + redA[1]) + (redA[2] + redA[3]);
            if (tid == 0) {
                g_nodes[(size_t)bA * NSTEPS + d] = nodeA;
                g_gval [(size_t)bA * NSTEPS + d] = gelu_exact(sA);
            }
            nodeA = nodeA * 2 + 1 + (sA >= 0.0f ? 1 : 0);
        }

        // Issue A's NEXT row load; it lands during B's phase. (Skip on last step.)
        if (d + 1 < NSTEPS) {
            const float4* wrA = Win4 + (size_t)nodeA * D4;
            wA0 = wrA[tid];
            wA1 = wrA[tid + 128];
            wA2 = wrA[tid + 256];
            wA3 = wrA[tid + 384];
        }

        // ---- Phase B: dot + reduce + select ----
        {
            float p = dot4(wB0, xB0);
            p += dot4(wB1, xB1);
            p += dot4(wB2, xB2);
            p += dot4(wB3, xB3);
            #pragma unroll
            for (int off = 16; off > 0; off >>= 1)
                p += __shfl_down_sync(0xffffffffu, p, off);
            if (lane == 0) redB[warp] = p;
            __syncthreads();
            float sB = (redB[0] + redB[1]) + (redB[2] + redB[3]);
            if (tid == 0) {
                g_nodes[(size_t)bB * NSTEPS + d] = nodeB;
                g_gval [(size_t)bB * NSTEPS + d] = gelu_exact(sB);
            }
            nodeB = nodeB * 2 + 1 + (sB >= 0.0f ? 1 : 0);
        }
    }
}

// Output accumulation: fully parallel, 12 independent row gathers per sample.
__global__ __launch_bounds__(128, 8) void out_kernel(
    float* __restrict__ out)
{
    const int b   = blockIdx.x;
    const int tid = threadIdx.x;

    const float4* __restrict__ Wt4 = reinterpret_cast<const float4*>(g_WoutT);

    int   nd[NSTEPS];
    float gg[NSTEPS];
    #pragma unroll
    for (int d = 0; d < NSTEPS; ++d) {
        nd[d] = g_nodes[(size_t)b * NSTEPS + d];
        gg[d] = g_gval [(size_t)b * NSTEPS + d];
    }

    float4 a0 = make_float4(0.f, 0.f, 0.f, 0.f);
    float4 a1 = make_float4(0.f, 0.f, 0.f, 0.f);
    float4 a2 = make_float4(0.f, 0.f, 0.f, 0.f);
    float4 a3 = make_float4(0.f, 0.f, 0.f, 0.f);

    #pragma unroll
    for (int d = 0; d < NSTEPS; ++d) {
        const float4* __restrict__ vr = Wt4 + (size_t)nd[d] * D4;
        float g = gg[d];
        fma4(a0, g, vr[tid]);
        fma4(a1, g, vr[tid + 128]);
        fma4(a2, g, vr[tid + 256]);
        fma4(a3, g, vr[tid + 384]);
    }

    float4* __restrict__ o4 = reinterpret_cast<float4*>(out) + (size_t)b * D4;
    o4[tid]       = a0;
    o4[tid + 128] = a1;
    o4[tid + 256] = a2;
    o4[tid + 384] = a3;
}

extern "C" void kernel_launch(void* const* d_in, const int* in_sizes, int n_in,
                              void* d_out, int out_size)
{
    const float* x    = (const float*)d_in[0];   // (8192, 2048)
    const float* Win  = (const float*)d_in[1];   // (4095, 2048)
    const float* Wout = (const float*)d_in[2];   // (2048, 4095)
    float* out = (float*)d_out;                  // (8192, 2048)

    // Fork a side stream so the transpose (depends only on W_out) overlaps
    // the route kernel (depends only on x, W_in). Standard capture-legal
    // event fork/join; handles are host resources (no device allocation).
    cudaStream_t s2;
    cudaStreamCreateWithFlags(&s2, cudaStreamNonBlocking);
    cudaEvent_t eFork, eJoin;
    cudaEventCreateWithFlags(&eFork, cudaEventDisableTiming);
    cudaEventCreateWithFlags(&eJoin, cudaEventDisableTiming);

    cudaEventRecord(eFork, 0);
    cudaStreamWaitEvent(s2, eFork, 0);

    dim3 tg((N_NODES + 63) / 64, DDIM / 64);
    transpose_wout<<<tg, 256, 0, s2>>>(Wout);
    cudaEventRecord(eJoin, s2);

    route_kernel<<<BATCH / 2, 128>>>(x, Win);

    cudaStreamWaitEvent(0, eJoin, 0);
    out_kernel<<<BATCH, 128>>>(out);
    // Note: s2/eFork/eJoin intentionally not destroyed here — destroying a
    // forked stream mid-capture would invalidate the graph. Handles are tiny
    // host-side resources; kernel_launch is invoked only a handful of times.
}

// round 11
// speedup vs baseline: 1.1055x; 1.0672x over previous
#include <cuda_runtime.h>
#include <math.h>

// FFF: fast-feedforward conditional tree MLP.
// B=8192, D_in=D_out=2048, depth 11 -> 12 routing steps, 4095 nodes.
//
// k1 transpose_wout: W_out -> g_WoutT on a forked stream (overlaps route).
// k2 route_kernel:   64-thread block per sample (12 blocks/SM -> 12 chains).
//                    x cached as 8 float4/thread; W_in row streamed as 8
//                    float4 chunks; xor-butterfly warp reduce (deterministic,
//                    all lanes converge) + 2-warp smem exchange.
// k3 out_kernel:     out[b] = sum_d g_d * W_outT[node_d]; 12 independent row
//                    gathers, latency-immune.

#define DEPTH    11
#define NSTEPS   (DEPTH + 1)
#define N_NODES  4095
#define DDIM     2048
#define D4       (DDIM / 4)     // 512 float4 per row
#define BATCH    8192
#define RT       64             // route block size

__device__ float g_WoutT[(size_t)N_NODES * DDIM];
__device__ int   g_nodes[(size_t)BATCH * NSTEPS];
__device__ float g_gval [(size_t)BATCH * NSTEPS];

// 64x64 tile transpose, 256 threads, coalesced both sides.
__global__ __launch_bounds__(256) void transpose_wout(const float* __restrict__ Wout) {
    __shared__ float tile[64][65];
    const int n0 = blockIdx.x * 64;
    const int o0 = blockIdx.y * 64;
    const int tid = threadIdx.x;

    #pragma unroll
    for (int k = 0; k < 16; ++k) {
        int e = k * 256 + tid;
        int ol = e >> 6;
        int nl = e & 63;
        int n = n0 + nl;
        float v = 0.f;
        if (n < N_NODES)
            v = Wout[(size_t)(o0 + ol) * N_NODES + n];
        tile[nl][ol] = v;
    }
    __syncthreads();

    #pragma unroll
    for (int k = 0; k < 16; ++k) {
        int e = k * 256 + tid;
        int nl = e >> 6;
        int ol = e & 63;
        int n = n0 + nl;
        if (n < N_NODES)
            g_WoutT[(size_t)n * DDIM + (o0 + ol)] = tile[nl][ol];
    }
}

__device__ __forceinline__ float dot4(float4 a, float4 b) {
    return fmaf(a.x, b.x, fmaf(a.y, b.y, fmaf(a.z, b.z, a.w * b.w)));
}

__device__ __forceinline__ void fma4(float4& a, float g, float4 v) {
    a.x = fmaf(g, v.x, a.x);
    a.y = fmaf(g, v.y, a.y);
    a.z = fmaf(g, v.z, a.z);
    a.w = fmaf(g, v.w, a.w);
}

__device__ __forceinline__ float gelu_exact(float s) {
    return 0.5f * s * (1.0f + erff(s * 0.70710678118654752f));
}

// 64 threads per block, one sample per block. 12 blocks/SM.
__global__ __launch_bounds__(RT, 12) void route_kernel(
    const float* __restrict__ x,
    const float* __restrict__ Win)
{
    const int b    = blockIdx.x;
    const int tid  = threadIdx.x;
    const int lane = tid & 31;
    const int warp = tid >> 5;

    const float4* __restrict__ Win4 = reinterpret_cast<const float4*>(Win);
    const float4* __restrict__ x4   = reinterpret_cast<const float4*>(x) + (size_t)b * D4;

    // x row: 8 float4 per thread, thread t owns indices t + 64*i.
    float4 xr[8];
    #pragma unroll
    for (int i = 0; i < 8; ++i)
        xr[i] = x4[tid + RT * i];

    __shared__ float red[2][2];

    int node = 0;
    #pragma unroll
    for (int d = 0; d < NSTEPS; ++d) {
        const float4* __restrict__ wr = Win4 + (size_t)node * D4;

        float p0 = 0.f, p1 = 0.f;
        #pragma unroll
        for (int i = 0; i < 8; i += 2) {
            p0 += dot4(wr[tid + RT * i],       xr[i]);
            p1 += dot4(wr[tid + RT * (i + 1)], xr[i + 1]);
        }
        float p = p0 + p1;

        // XOR butterfly: fp add is commutative, so every lane performs the
        // same pair-tree and converges to a bit-identical warp sum.
        #pragma unroll
        for (int off = 16; off > 0; off >>= 1)
            p += __shfl_xor_sync(0xffffffffu, p, off);

        if (lane == 0) red[d & 1][warp] = p;
        __syncthreads();

        float score = red[d & 1][0] + red[d & 1][1];

        if (tid == 0) {
            g_nodes[(size_t)b * NSTEPS + d] = node;
            g_gval [(size_t)b * NSTEPS + d] = gelu_exact(score);
        }

        node = node * 2 + 1 + (score >= 0.0f ? 1 : 0);
    }
}

// Output accumulation: fully parallel, 12 independent row gathers per sample.
__global__ __launch_bounds__(128, 8) void out_kernel(
    float* __restrict__ out)
{
    const int b   = blockIdx.x;
    const int tid = threadIdx.x;

    const float4* __restrict__ Wt4 = reinterpret_cast<const float4*>(g_WoutT);

    int   nd[NSTEPS];
    float gg[NSTEPS];
    #pragma unroll
    for (int d = 0; d < NSTEPS; ++d) {
        nd[d] = g_nodes[(size_t)b * NSTEPS + d];
        gg[d] = g_gval [(size_t)b * NSTEPS + d];
    }

    float4 a0 = make_float4(0.f, 0.f, 0.f, 0.f);
    float4 a1 = make_float4(0.f, 0.f, 0.f, 0.f);
    float4 a2 = make_float4(0.f, 0.f, 0.f, 0.f);
    float4 a3 = make_float4(0.f, 0.f, 0.f, 0.f);

    #pragma unroll
    for (int d = 0; d < NSTEPS; ++d) {
        const float4* __restrict__ vr = Wt4 + (size_t)nd[d] * D4;
        float g = gg[d];
        fma4(a0, g, vr[tid]);
        fma4(a1, g, vr[tid + 128]);
        fma4(a2, g, vr[tid + 256]);
        fma4(a3, g, vr[tid + 384]);
    }

    float4* __restrict__ o4 = reinterpret_cast<float4*>(out) + (size_t)b * D4;
    o4[tid]       = a0;
    o4[tid + 128] = a1;
    o4[tid + 256] = a2;
    o4[tid + 384] = a3;
}

extern "C" void kernel_launch(void* const* d_in, const int* in_sizes, int n_in,
                              void* d_out, int out_size)
{
    const float* x    = (const float*)d_in[0];   // (8192, 2048)
    const float* Win  = (const float*)d_in[1];   // (4095, 2048)
    const float* Wout = (const float*)d_in[2];   // (2048, 4095)
    float* out = (float*)d_out;                  // (8192, 2048)

    // Fork: transpose (W_out only) runs concurrently with route (x, W_in).
    cudaStream_t s2;
    cudaStreamCreateWithFlags(&s2, cudaStreamNonBlocking);
    cudaEvent_t eFork, eJoin;
    cudaEventCreateWithFlags(&eFork, cudaEventDisableTiming);
    cudaEventCreateWithFlags(&eJoin, cudaEventDisableTiming);

    cudaEventRecord(eFork, 0);
    cudaStreamWaitEvent(s2, eFork, 0);

    dim3 tg((N_NODES + 63) / 64, DDIM / 64);
    transpose_wout<<<tg, 256, 0, s2>>>(Wout);
    cudaEventRecord(eJoin, s2);

    route_kernel<<<BATCH, RT>>>(x, Win);

    cudaStreamWaitEvent(0, eJoin, 0);
    out_kernel<<<BATCH, 128>>>(out);
}